// round 3
// baseline (speedup 1.0000x reference)
#include <cuda_runtime.h>

#define SEQ   4096
#define CIN   7
#define NUMK  74
#define KH    8
#define KW    3
#define D     1536
#define HALFD 768
#define TLEN  (SEQ * KW)   // 12288
#define SPER  8            // s-rows per block

// ---------------- precomputed tables (device globals; no allocation) ----------------
// A[hi][i] = (sin(64*hi*div_i), cos(64*hi*div_i)),  B[lo][i] = (sin(lo*div_i), cos(lo*div_i))
__device__ float g_A[64][HALFD][2];
__device__ float g_B[64][HALFD][2];
// T2[a*7+b][f] = g(a)[f] + g(b)[f]   (temporal pair sums; indices are 0..6)
__device__ float g_T2[49][D];

__global__ void init_tables_kernel()
{
    int idx = blockIdx.x * blockDim.x + threadIdx.x;
    const float cexp = (float)(-9.210340371976184 / 1536.0); // -ln(10000)/d

    if (idx < 64 * HALFD) {
        int i = idx % HALFD;
        int r = idx / HALFD;
        float div = expf((2.0f * (float)i) * cexp);
        float sh, ch, sl, cl;
        sincosf((float)(64 * r) * div, &sh, &ch);
        g_A[r][i][0] = sh; g_A[r][i][1] = ch;
        sincosf((float)r * div, &sl, &cl);
        g_B[r][i][0] = sl; g_B[r][i][1] = cl;
    }
    if (idx < 49 * HALFD) {
        int i = idx % HALFD;
        int p = idx / HALFD;
        int a = p / 7, b = p % 7;
        float div = expf((2.0f * (float)i) * cexp);
        float sa, ca, sb, cb;
        sincosf((float)a * div, &sa, &ca);
        sincosf((float)b * div, &sb, &cb);
        g_T2[p][2 * i]     = sa + sb;
        g_T2[p][2 * i + 1] = ca + cb;
    }
}

// ---------------- main kernel: 384 threads, thread = (j, lane) owns one float4 per row ----------------
__global__ __launch_bounds__(384, 2) void embed_kernel(
    const float* __restrict__ x,       // (4096, 7)
    const float* __restrict__ kern,    // (74, 8, 3)
    const int*   __restrict__ xm,      // (4096, 4)
    float*       __restrict__ out)     // (4096, 1536)
{
    __shared__ float wcs[KH][76];      // [k][o], padded
    __shared__ float sx[CIN][36];      // window: 3*SPER+7 = 31 used
    __shared__ int   t2i[SPER][2];     // temporal pair-table indices per row

    const int s0   = blockIdx.x * SPER;   // aligned: hi = s>>6 constant in block
    const int tid  = threadIdx.x;
    const int lane = tid & 127;           // 0..127
    const int jj   = tid >> 7;            // 0..2

    // ---- stage weights: wc[o][k] = kern[o*24 + k*3 + 1]
    for (int e = tid; e < NUMK * KH; e += 384) {
        int o = e / KH, k = e - o * KH;
        wcs[k][o] = kern[o * (KH * KW) + k * KW + 1];
    }
    // ---- stage x window: i in [0,31), t = 3*s0 - 4 + i
    if (tid < CIN * 31) {
        int c = tid / 31, i = tid - c * 31;
        int t = 3 * s0 - 4 + i;
        float v = 0.0f;
        if (t >= 0 && t < TLEN) {
            int row = t / 3 + t % 3;
            if (row > SEQ - 1) row = SEQ - 1;
            v = x[row * CIN + c];
        }
        sx[c][i] = v;
    }
    // ---- stage temporal table indices
    if (tid < SPER) {
        int s = s0 + tid;
        int i0 = xm[s * 4 + 0], i1 = xm[s * 4 + 1],
            i2 = xm[s * 4 + 2], i3 = xm[s * 4 + 3];
        t2i[tid][0] = i3 * 7 + i2;
        t2i[tid][1] = i1 * 7 + i0;
    }
    __syncthreads();

    const int g0 = 4 * lane;              // 0..508
    const int f  = jj * 512 + g0;         // this thread's column

    // per-lane (c, o); a thread spans at most 2 distinct c
    int cc[4], oo[4];
#pragma unroll
    for (int le = 0; le < 4; le++) {
        int gg = g0 + le;
        if (gg == 511) { cc[le] = 0; oo[le] = NUMK - 1; }
        else           { cc[le] = gg / 73; oo[le] = gg - cc[le] * 73; }
    }
    const int ca = cc[0], cb = cc[3];
    bool sel[4];
#pragma unroll
    for (int le = 0; le < 4; le++) sel[le] = (cc[le] == ca);

    // weights into registers (reused across all 8 rows)
    float wr[4][8];
#pragma unroll
    for (int le = 0; le < 4; le++)
#pragma unroll
        for (int k = 0; k < 8; k++)
            wr[le][k] = wcs[k][oo[le]];

    // pe hi-part: one float4, constant across the block's rows
    const float4 av = *(const float4*)(&g_A[s0 >> 6][0][0] + f);

    const float* __restrict__ Bp   = &g_B[s0 & 63][0][0] + f;  // +1536/row, no wrap
    float*       __restrict__ outp = out + (size_t)s0 * D + f;

#pragma unroll 2
    for (int r = 0; r < SPER; r++) {
        const float4 bv = *(const float4*)Bp;
        const float4 ta = *(const float4*)(g_T2[t2i[r][0]] + f);
        const float4 tb = *(const float4*)(g_T2[t2i[r][1]] + f);

        const int base = 3 * r + jj;
        float sa8[8], sb8[8];
#pragma unroll
        for (int k = 0; k < 8; k++) {
            sa8[k] = sx[ca][base + k];
            sb8[k] = sx[cb][base + k];
        }

        float acc[4];
#pragma unroll
        for (int le = 0; le < 4; le++) {
            float a = 0.0f;
#pragma unroll
            for (int k = 0; k < 8; k++) {
                float v = sel[le] ? sa8[k] : sb8[k];
                a += v * wr[le][k];
            }
            acc[le] = a;
        }

        // pe via angle addition
        const float pe0 = av.x * bv.y + av.y * bv.x;   // sin
        const float pe1 = av.y * bv.y - av.x * bv.x;   // cos
        const float pe2 = av.z * bv.w + av.w * bv.z;
        const float pe3 = av.w * bv.w - av.z * bv.z;

        float4 res;
        res.x = acc[0] + pe0 + ta.x + tb.x;
        res.y = acc[1] + pe1 + ta.y + tb.y;
        res.z = acc[2] + pe2 + ta.z + tb.z;
        res.w = acc[3] + pe3 + ta.w + tb.w;
        *(float4*)outp = res;

        Bp   += D;
        outp += D;
    }
}

// ---------------- launch ----------------
extern "C" void kernel_launch(void* const* d_in, const int* in_sizes, int n_in,
                              void* d_out, int out_size)
{
    const float* x     = nullptr;
    const float* kern  = nullptr;
    const int*   xmark = nullptr;
    for (int i = 0; i < n_in; i++) {
        if      (in_sizes[i] == SEQ * CIN)        x     = (const float*)d_in[i];
        else if (in_sizes[i] == NUMK * KH * KW)   kern  = (const float*)d_in[i];
        else if (in_sizes[i] == SEQ * 4)          xmark = (const int*)d_in[i];
    }

    init_tables_kernel<<<(64 * HALFD + 255) / 256, 256>>>();
    embed_kernel<<<SEQ / SPER, 384>>>(x, kern, xmark, (float*)d_out);
}

// round 4
// speedup vs baseline: 1.1157x; 1.1157x over previous
#include <cuda_runtime.h>

#define SEQ   4096
#define CIN   7
#define NUMK  74
#define KH    8
#define KW    3
#define D     1536
#define HALFD 768
#define TLEN  (SEQ * KW)   // 12288
#define SPER  8            // s-rows per block
#define NH    (3 * SPER)   // 24 conv h-values per block

// ---------------- precomputed tables (device globals; no allocation) ----------------
// A[hi][i] = (sin(64*hi*div_i), cos(64*hi*div_i)),  B[lo][i] = (sin(lo*div_i), cos(lo*div_i))
__device__ float g_A[64][HALFD][2];
__device__ float g_B[64][HALFD][2];
// T2[a*7+b][f] = g(a)[f] + g(b)[f]   (temporal pair sums; indices are 0..6)
__device__ float g_T2[49][D];

__global__ void init_tables_kernel()
{
    int idx = blockIdx.x * blockDim.x + threadIdx.x;
    const float cexp = (float)(-9.210340371976184 / 1536.0); // -ln(10000)/d

    if (idx < 64 * HALFD) {
        int i = idx % HALFD;
        int r = idx / HALFD;
        float div = expf((2.0f * (float)i) * cexp);
        float sh, ch, sl, cl;
        sincosf((float)(64 * r) * div, &sh, &ch);
        g_A[r][i][0] = sh; g_A[r][i][1] = ch;
        sincosf((float)r * div, &sl, &cl);
        g_B[r][i][0] = sl; g_B[r][i][1] = cl;
    }
    if (idx < 49 * HALFD) {
        int i = idx % HALFD;
        int p = idx / HALFD;
        int a = p / 7, b = p % 7;
        float div = expf((2.0f * (float)i) * cexp);
        float sa, ca, sb, cb;
        sincosf((float)a * div, &sa, &ca);
        sincosf((float)b * div, &sb, &cb);
        g_T2[p][2 * i]     = sa + sb;
        g_T2[p][2 * i + 1] = ca + cb;
    }
}

// dynamic smem layout (floats):
//   convS [NH][512]      : 12288
//   wcsS  [KH][76]       : 608
//   sxS   [CIN][32]      : 224
//   t2iS  [SPER][2] ints : 16 ints
#define SM_CONV   0
#define SM_WCS    12288
#define SM_SX     (SM_WCS + 608)
#define SM_T2I    (SM_SX + 224)
#define SMEM_BYTES ((SM_T2I) * 4 + SPER * 2 * 4 + 64)

// ---------------- main kernel: two-phase, 256 threads, 8 rows/block ----------------
__global__ __launch_bounds__(256, 4) void embed_kernel(
    const float* __restrict__ x,       // (4096, 7)
    const float* __restrict__ kern,    // (74, 8, 3)
    const int*   __restrict__ xm,      // (4096, 4)
    float*       __restrict__ out)     // (4096, 1536)
{
    extern __shared__ float smem[];
    float* __restrict__ convS = smem + SM_CONV;   // [NH][512], h-major
    float* __restrict__ wcsS  = smem + SM_WCS;    // [k][76]
    float* __restrict__ sxS   = smem + SM_SX;     // [c][32], 31 used
    int*   __restrict__ t2iS  = (int*)(smem + SM_T2I);

    const int s0  = blockIdx.x * SPER;   // aligned: hi = s>>6 constant in block
    const int tid = threadIdx.x;

    // ---- stage weights: wc[o][k] = kern[o*24 + k*3 + 1]
    for (int e = tid; e < NUMK * KH; e += 256) {
        int o = e / KH, k = e - o * KH;
        wcsS[k * 76 + o] = kern[o * (KH * KW) + k * KW + 1];
    }
    // ---- stage x window: i in [0,31), t = 3*s0 - 4 + i
    if (tid < CIN * 31) {
        int c = tid / 31, i = tid - c * 31;
        int t = 3 * s0 - 4 + i;
        float v = 0.0f;
        if (t >= 0 && t < TLEN) {
            int row = t / 3 + t % 3;
            if (row > SEQ - 1) row = SEQ - 1;
            v = x[row * CIN + c];
        }
        sxS[c * 32 + i] = v;
    }
    // ---- stage temporal table indices
    if (tid < SPER) {
        int s = s0 + tid;
        int i0 = xm[s * 4 + 0], i1 = xm[s * 4 + 1],
            i2 = xm[s * 4 + 2], i3 = xm[s * 4 + 3];
        t2iS[2 * tid]     = i3 * 7 + i2;
        t2iS[2 * tid + 1] = i1 * 7 + i0;
    }
    __syncthreads();

    // =========== Phase 1: conv into smem, thread owns g = tid and g = tid+256 ==========
#pragma unroll
    for (int gi = 0; gi < 2; gi++) {
        const int g = tid + gi * 256;        // 0..511
        int c, o;
        if (g == 511) { c = 0; o = NUMK - 1; }
        else          { c = g / 73; o = g - c * 73; }

        float w[8];
#pragma unroll
        for (int k = 0; k < 8; k++) w[k] = wcsS[k * 76 + o];

        const float* __restrict__ sxc = sxS + c * 32;
        float v[8];
#pragma unroll
        for (int k = 0; k < 8; k++) v[k] = sxc[k];

#pragma unroll
        for (int h = 0; h < NH; h++) {
            float acc = 0.0f;
#pragma unroll
            for (int k = 0; k < 8; k++) acc += v[(h + k) & 7] * w[k];
            convS[h * 512 + g] = acc;
            if (h < NH - 1) v[h & 7] = sxc[h + 8];
        }
    }
    __syncthreads();

    // =========== Phase 2: stream tables + conv, add, store ==========
    const int lane = tid & 127;          // 0..127 -> g0
    const int half = tid >> 7;           // 0..1   -> rows r0..r0+3
    const int g0   = 4 * lane;
    const int r0   = half * 4;
    const int hi   = s0 >> 6;
    const int lo0  = s0 & 63;

    // row table indices into registers
    int ia[4], ib[4];
#pragma unroll
    for (int rr = 0; rr < 4; rr++) {
        ia[rr] = t2iS[2 * (r0 + rr)];
        ib[rr] = t2iS[2 * (r0 + rr) + 1];
    }

#pragma unroll
    for (int jj = 0; jj < 3; jj++) {
        const int f = jj * 512 + g0;
        const float4 av = *(const float4*)(&g_A[hi][0][0] + f);

#pragma unroll
        for (int rr = 0; rr < 4; rr++) {
            const int r = r0 + rr;
            const float4 cv = *(const float4*)(convS + (3 * r + jj) * 512 + g0);
            const float4 bv = *(const float4*)(&g_B[lo0 + r][0][0] + f);
            const float4 ta = *(const float4*)(g_T2[ia[rr]] + f);
            const float4 tb = *(const float4*)(g_T2[ib[rr]] + f);

            const float pe0 = av.x * bv.y + av.y * bv.x;   // sin
            const float pe1 = av.y * bv.y - av.x * bv.x;   // cos
            const float pe2 = av.z * bv.w + av.w * bv.z;
            const float pe3 = av.w * bv.w - av.z * bv.z;

            float4 res;
            res.x = cv.x + pe0 + ta.x + tb.x;
            res.y = cv.y + pe1 + ta.y + tb.y;
            res.z = cv.z + pe2 + ta.z + tb.z;
            res.w = cv.w + pe3 + ta.w + tb.w;
            *(float4*)(out + (size_t)(s0 + r) * D + f) = res;
        }
    }
}

// ---------------- launch ----------------
extern "C" void kernel_launch(void* const* d_in, const int* in_sizes, int n_in,
                              void* d_out, int out_size)
{
    const float* x     = nullptr;
    const float* kern  = nullptr;
    const int*   xmark = nullptr;
    for (int i = 0; i < n_in; i++) {
        if      (in_sizes[i] == SEQ * CIN)        x     = (const float*)d_in[i];
        else if (in_sizes[i] == NUMK * KH * KW)   kern  = (const float*)d_in[i];
        else if (in_sizes[i] == SEQ * 4)          xmark = (const int*)d_in[i];
    }

    cudaFuncSetAttribute(embed_kernel,
                         cudaFuncAttributeMaxDynamicSharedMemorySize, SMEM_BYTES);

    init_tables_kernel<<<(64 * HALFD + 255) / 256, 256>>>();
    embed_kernel<<<SEQ / SPER, 256, SMEM_BYTES>>>(x, kern, xmark, (float*)d_out);
}